// round 12
// baseline (speedup 1.0000x reference)
#include <cuda_runtime.h>
#include <cuda_fp16.h>
#include <stdint.h>

#define HD      256
#define N_DRUG  50000
#define N_TGT   20000
#define NB64_D  782   // ceil(50000/64)
#define NB64_T  313   // ceil(20000/64)

// ---------------- device scratch (no allocation allowed) -------------------
__device__ __align__(16) __half g_ud[(size_t)N_DRUG * HD];   // fp16, b1 folded in
__device__ __align__(16) __half g_ut[(size_t)N_TGT  * HD];
// W1 transposed to [n][k] fp16 (K-contiguous rows => col-major B for mma.sync)
__device__ __align__(16) __half g_wd[HD * HD];
__device__ __align__(16) __half g_wt[HD * HD];
__device__ int g_idx64;

__device__ __forceinline__ uint32_t smem_u32(const void* p) {
    uint32_t a;
    asm("{ .reg .u64 t; cvta.to.shared.u64 t, %1; cvt.u32.u64 %0, t; }" : "=r"(a) : "l"(p));
    return a;
}
#define CP_ASYNC_16(dst, src) \
    asm volatile("cp.async.cg.shared.global [%0], [%1], 16;" :: "r"(dst), "l"(src))
#define CP_ASYNC_COMMIT() asm volatile("cp.async.commit_group;")
#define CP_ASYNC_WAIT1()  asm volatile("cp.async.wait_group 1;")

// ---------------------------------------------------------------------------
// W1 prep: 32x32 SMEM-tiled transpose [k][n] -> [n][k] + fp32->fp16.
// Coalesced reads AND writes (R6/R8 version scattered 2B stores at 512B
// stride -> 32 sectors/warp; that was the 5.6us). Block 0 warp 0 also does
// the int64-vs-int32 index-width detect (ballot).
// ---------------------------------------------------------------------------
__global__ void prep_w1_kernel(const float* __restrict__ W1,
                               const unsigned long long* __restrict__ row) {
    if (blockIdx.x == 0 && threadIdx.x < 32) {
        unsigned long long v0 = row[threadIdx.x];
        unsigned long long v1 = row[threadIdx.x + 32];
        int bad = (v0 >= (unsigned long long)N_DRUG) ||
                  (v1 >= (unsigned long long)N_DRUG);
        unsigned m = __ballot_sync(0xffffffffu, bad);
        if (threadIdx.x == 0) g_idx64 = (m == 0);
    }
    __shared__ float tile[32][33];
    const int bx = blockIdx.x & 7;     // n-tile (8 of 32)
    const int by = blockIdx.x >> 3;    // k-tile (16 of 32)
    const int tx = threadIdx.x & 31;
    const int ty = threadIdx.x >> 5;   // 0..7
    const int n0 = bx * 32, k0 = by * 32;

    #pragma unroll
    for (int i = 0; i < 4; ++i)
        tile[ty + i * 8][tx] = W1[(size_t)(k0 + ty + i * 8) * HD + n0 + tx];
    __syncthreads();

    #pragma unroll
    for (int i = 0; i < 4; ++i) {
        int n = n0 + ty + i * 8;
        int k = k0 + tx;
        __half h = __float2half_rn(tile[tx][ty + i * 8]);
        if (k < HD) g_wd[n * HD + k]        = h;
        else        g_wt[n * HD + (k - HD)] = h;
    }
}

// ---------------------------------------------------------------------------
// HMMA GEMM:  U[M,256](fp16) = A[M,256](fp32) @ W[256,256]  (+b1 for drug)
// 64m x 256n CTA tile, BK=32. B: 3-stage cp.async pipeline (wait_group 1,
// 2-chunk lead). A: single-chunk register lookahead (R6 register footprint).
// 8 warps = 2m x 4n (32x64 each).
// ---------------------------------------------------------------------------
#define APAD   40                          // padded k-stride in halves
#define A_BYTES (2 * 64 * APAD * 2)        // 10240
#define B_BYTES (3 * 256 * APAD * 2)       // 61440
#define SMEM_TOTAL (A_BYTES + B_BYTES)     // 71680

__global__ __launch_bounds__(256, 2)
void gemm_hmma_kernel(const float* __restrict__ zd, const float* __restrict__ zt,
                      const float* __restrict__ b1) {
    extern __shared__ char smem[];
    const uint32_t sbase = smem_u32(smem);
    const uint32_t bbase = sbase + A_BYTES;

    const int blk = blockIdx.x;
    const float* A; const __half* B; __half* U; int M, bm; const float* bias;
    if (blk < NB64_D) { A = zd; B = g_wd; U = g_ud; M = N_DRUG; bm = blk * 64; bias = b1; }
    else { A = zt; B = g_wt; U = g_ut; M = N_TGT; bm = (blk - NB64_D) * 64; bias = nullptr; }

    const int tid  = threadIdx.x;
    const int lane = tid & 31;
    const int wid  = tid >> 5;
    const int wm   = (wid & 1) * 32;   // warp m offset (0/32)
    const int wn   = (wid >> 1) * 64;  // warp n offset (0/64/128/192)

    // A load mapping: 4 threads per row, 8 fp32 (2 float4) each
    const int arow = tid >> 2, aseg = tid & 3;
    const int ag   = min(bm + arow, M - 1);
    const float4* Ag = reinterpret_cast<const float4*>(A + (size_t)ag * HD);

    float acc[2][8][4];
    #pragma unroll
    for (int i = 0; i < 2; ++i)
        #pragma unroll
        for (int j = 0; j < 8; ++j)
            #pragma unroll
            for (int q = 0; q < 4; ++q) acc[i][j][q] = 0.f;

    float4 va[2];   // single-chunk A lookahead (keeps register count at R6 level)

    auto load_a = [&](int ck) {
        va[0] = Ag[ck * 8 + aseg * 2];
        va[1] = Ag[ck * 8 + aseg * 2 + 1];
    };
    auto store_a = [&](int buf) {
        uint32_t h[4];
        #pragma unroll
        for (int i = 0; i < 2; ++i) {
            __half2 p0 = __float22half2_rn(make_float2(va[i].x, va[i].y));
            __half2 p1 = __float22half2_rn(make_float2(va[i].z, va[i].w));
            h[2 * i]     = *reinterpret_cast<uint32_t*>(&p0);
            h[2 * i + 1] = *reinterpret_cast<uint32_t*>(&p1);
        }
        *reinterpret_cast<uint4*>(smem + (buf * 64 + arow) * (APAD * 2) + aseg * 16) =
            make_uint4(h[0], h[1], h[2], h[3]);
    };
    auto issue_b = [&](int ck) {
        const int st = ck % 3;
        #pragma unroll
        for (int i = 0; i < 4; ++i) {
            int idx = i * 256 + tid;          // 0..1023
            int n = idx >> 2, c = idx & 3;
            uint32_t dst = bbase + (st * 256 + n) * (APAD * 2) + c * 16;
            const __half* src = B + (size_t)n * HD + ck * 32 + c * 8;
            CP_ASYNC_16(dst, src);
        }
        CP_ASYNC_COMMIT();
    };

    // prologue: B(0),B(1) in flight; A(0) -> SMEM; A(1) -> regs; wait B(0)
    load_a(0);
    issue_b(0);
    issue_b(1);
    store_a(0);
    load_a(1);
    CP_ASYNC_WAIT1();
    __syncthreads();

    #pragma unroll 1
    for (int ck = 0; ck < 8; ++ck) {
        const int buf = ck & 1;
        const int st  = ck % 3;

        if (ck < 6) issue_b(ck + 2);          // keep 2-chunk B lead
        if (ck < 7) store_a(buf ^ 1);         // va holds A(ck+1); buffer safe (synced)
        if (ck < 6) load_a(ck + 2);           // refill va for next iteration

        #pragma unroll
        for (int ks = 0; ks < 2; ++ks) {
            uint32_t af[2][4], bf[4][4];
            #pragma unroll
            for (int mt = 0; mt < 2; ++mt) {
                uint32_t addr = sbase + (buf * 64 + wm + mt * 16 + (lane & 15)) * (APAD * 2)
                                      + (ks * 16 + (lane >> 4) * 8) * 2;
                asm volatile("ldmatrix.sync.aligned.m8n8.x4.shared.b16 {%0,%1,%2,%3}, [%4];"
                             : "=r"(af[mt][0]), "=r"(af[mt][1]), "=r"(af[mt][2]), "=r"(af[mt][3])
                             : "r"(addr));
            }
            #pragma unroll
            for (int q = 0; q < 4; ++q) {
                uint32_t addr = bbase + (st * 256 + wn + q * 16 + (lane & 15)) * (APAD * 2)
                                      + (ks * 16 + (lane >> 4) * 8) * 2;
                asm volatile("ldmatrix.sync.aligned.m8n8.x4.shared.b16 {%0,%1,%2,%3}, [%4];"
                             : "=r"(bf[q][0]), "=r"(bf[q][1]), "=r"(bf[q][2]), "=r"(bf[q][3])
                             : "r"(addr));
            }
            #pragma unroll
            for (int mt = 0; mt < 2; ++mt)
                #pragma unroll
                for (int nt = 0; nt < 8; ++nt) {
                    const int q = nt >> 1, s = nt & 1;
                    asm volatile(
                        "mma.sync.aligned.m16n8k16.row.col.f32.f16.f16.f32 "
                        "{%0,%1,%2,%3}, {%4,%5,%6,%7}, {%8,%9}, {%0,%1,%2,%3};"
                        : "+f"(acc[mt][nt][0]), "+f"(acc[mt][nt][1]),
                          "+f"(acc[mt][nt][2]), "+f"(acc[mt][nt][3])
                        : "r"(af[mt][0]), "r"(af[mt][1]), "r"(af[mt][2]), "r"(af[mt][3]),
                          "r"(bf[q][s]), "r"(bf[q][s + 2]));
                }
        }

        if (ck < 7) {
            CP_ASYNC_WAIT1();   // B(ck+1) arrived (only B(ck+2) still in flight)
            __syncthreads();
        }
    }

    // per-column bias (b1 folded into the drug table)
    float2 bv[8];
    #pragma unroll
    for (int nt = 0; nt < 8; ++nt) bv[nt] = make_float2(0.f, 0.f);
    if (bias) {
        #pragma unroll
        for (int nt = 0; nt < 8; ++nt)
            bv[nt] = *reinterpret_cast<const float2*>(bias + wn + nt * 8 + (lane & 3) * 2);
    }

    // epilogue: fp32 acc (+bias) -> fp16 U
    #pragma unroll
    for (int mt = 0; mt < 2; ++mt) {
        #pragma unroll
        for (int hr = 0; hr < 2; ++hr) {
            int r = bm + wm + mt * 16 + hr * 8 + (lane >> 2);
            if (r < M) {
                __half* up = U + (size_t)r * HD + wn + (lane & 3) * 2;
                #pragma unroll
                for (int nt = 0; nt < 8; ++nt) {
                    __half2 v = __float22half2_rn(
                        make_float2(acc[mt][nt][hr * 2] + bv[nt].x,
                                    acc[mt][nt][hr * 2 + 1] + bv[nt].y));
                    *reinterpret_cast<__half2*>(up + nt * 8) = v;
                }
            }
        }
    }
}

// ---------------------------------------------------------------------------
// Edge kernel: out[e] = relu(u_d[row[e]] + u_t[col[e]]) . W2 + b2   (b1 folded)
// 8 lanes per edge (4 edges/warp); MLP=8 per thread, 3-shuffle reduction.
// ---------------------------------------------------------------------------
__global__ __launch_bounds__(256)
void edge_kernel(const void* __restrict__ rowp, const void* __restrict__ colp,
                 const float* __restrict__ W2, const float* __restrict__ b2,
                 float* __restrict__ out, int E) {
    __shared__ float s_w2[HD];
    const int tid = threadIdx.x;
    s_w2[tid] = W2[tid];
    __syncthreads();

    const int lane = tid & 31;
    const int wid  = tid >> 5;
    const int sub  = lane & 7;
    const int g    = lane >> 3;

    float w2r[32];
    #pragma unroll
    for (int i = 0; i < 4; ++i) {
        float4 v0 = *reinterpret_cast<const float4*>(&s_w2[(i * 8 + sub) * 8]);
        float4 v1 = *reinterpret_cast<const float4*>(&s_w2[(i * 8 + sub) * 8 + 4]);
        w2r[i * 8 + 0] = v0.x; w2r[i * 8 + 1] = v0.y;
        w2r[i * 8 + 2] = v0.z; w2r[i * 8 + 3] = v0.w;
        w2r[i * 8 + 4] = v1.x; w2r[i * 8 + 5] = v1.y;
        w2r[i * 8 + 6] = v1.z; w2r[i * 8 + 7] = v1.w;
    }
    const float bias2 = b2[0];
    const bool idx64 = (g_idx64 != 0);
    const __half2 zero2 = __float2half2_rn(0.f);

    for (int e = blockIdx.x * 32 + wid * 4 + g; e < E; e += gridDim.x * 32) {
        long long r, c;
        if (idx64) {
            r = reinterpret_cast<const long long*>(rowp)[e];
            c = reinterpret_cast<const long long*>(colp)[e];
        } else {
            r = reinterpret_cast<const int*>(rowp)[e];
            c = reinterpret_cast<const int*>(colp)[e];
        }
        const uint4* ap = reinterpret_cast<const uint4*>(g_ud + (size_t)r * HD);
        const uint4* bp = reinterpret_cast<const uint4*>(g_ut + (size_t)c * HD);

        uint4 av[4], bv[4];
        #pragma unroll
        for (int i = 0; i < 4; ++i) av[i] = ap[i * 8 + sub];
        #pragma unroll
        for (int i = 0; i < 4; ++i) bv[i] = bp[i * 8 + sub];

        float sum = 0.f;
        #pragma unroll
        for (int i = 0; i < 4; ++i) {
            const __half2* ah = reinterpret_cast<const __half2*>(&av[i]);
            const __half2* bh = reinterpret_cast<const __half2*>(&bv[i]);
            #pragma unroll
            for (int j = 0; j < 4; ++j) {
                __half2 h = __hmax2(__hadd2(ah[j], bh[j]), zero2);
                float2 f = __half22float2(h);
                sum = fmaf(f.x, w2r[i * 8 + j * 2],     sum);
                sum = fmaf(f.y, w2r[i * 8 + j * 2 + 1], sum);
            }
        }

        sum += __shfl_xor_sync(0xffffffffu, sum, 4);
        sum += __shfl_xor_sync(0xffffffffu, sum, 2);
        sum += __shfl_xor_sync(0xffffffffu, sum, 1);
        if (sub == 0) out[e] = sum + bias2;
    }
}

// ---------------------------------------------------------------------------
// inputs: 0=z_drug 1=z_target 2=row 3=col 4=W1[512,256] 5=b1 6=W2 7=b2
// ---------------------------------------------------------------------------
extern "C" void kernel_launch(void* const* d_in, const int* in_sizes, int n_in,
                              void* d_out, int out_size) {
    const float* z_drug   = (const float*)d_in[0];
    const float* z_target = (const float*)d_in[1];
    const void*  rowp     = d_in[2];
    const void*  colp     = d_in[3];
    const float* W1       = (const float*)d_in[4];
    const float* b1       = (const float*)d_in[5];
    const float* W2       = (const float*)d_in[6];
    const float* b2       = (const float*)d_in[7];
    float* out = (float*)d_out;
    const int E = out_size;

    cudaFuncSetAttribute(gemm_hmma_kernel,
                         cudaFuncAttributeMaxDynamicSharedMemorySize, SMEM_TOTAL);

    prep_w1_kernel<<<128, 256>>>(W1, (const unsigned long long*)rowp);
    gemm_hmma_kernel<<<NB64_D + NB64_T, 256, SMEM_TOTAL>>>(z_drug, z_target, b1);
    edge_kernel<<<2048, 256>>>(rowp, colp, W2, b2, out, E);
}

// round 13
// speedup vs baseline: 1.0010x; 1.0010x over previous
#include <cuda_runtime.h>
#include <cuda_fp16.h>
#include <stdint.h>

#define HD      256
#define N_DRUG  50000
#define N_TGT   20000
#define NB64_D  782   // ceil(50000/64)
#define NB64_T  313   // ceil(20000/64)

// ---------------- device scratch (no allocation allowed) -------------------
__device__ __align__(16) __half g_ud[(size_t)N_DRUG * HD];   // fp16, b1 folded in
__device__ __align__(16) __half g_ut[(size_t)N_TGT  * HD];
// W1 transposed to [n][k] fp16 (K-contiguous rows => col-major B for mma.sync)
__device__ __align__(16) __half g_wd[HD * HD];
__device__ __align__(16) __half g_wt[HD * HD];
__device__ int g_idx64;

__device__ __forceinline__ uint32_t smem_u32(const void* p) {
    uint32_t a;
    asm("{ .reg .u64 t; cvta.to.shared.u64 t, %1; cvt.u32.u64 %0, t; }" : "=r"(a) : "l"(p));
    return a;
}
#define CP_ASYNC_16(dst, src) \
    asm volatile("cp.async.cg.shared.global [%0], [%1], 16;" :: "r"(dst), "l"(src))
#define CP_ASYNC_COMMIT() asm volatile("cp.async.commit_group;")
#define CP_ASYNC_WAIT1()  asm volatile("cp.async.wait_group 1;")

// ---------------------------------------------------------------------------
// W1 prep: 32x32 SMEM-tiled transpose [k][n] -> [n][k] + fp32->fp16.
// Coalesced reads AND writes (R6/R8 version scattered 2B stores at 512B
// stride -> 32 sectors/warp; that was the 5.6us). Block 0 warp 0 also does
// the int64-vs-int32 index-width detect (ballot).
// ---------------------------------------------------------------------------
__global__ void prep_w1_kernel(const float* __restrict__ W1,
                               const unsigned long long* __restrict__ row) {
    if (blockIdx.x == 0 && threadIdx.x < 32) {
        unsigned long long v0 = row[threadIdx.x];
        unsigned long long v1 = row[threadIdx.x + 32];
        int bad = (v0 >= (unsigned long long)N_DRUG) ||
                  (v1 >= (unsigned long long)N_DRUG);
        unsigned m = __ballot_sync(0xffffffffu, bad);
        if (threadIdx.x == 0) g_idx64 = (m == 0);
    }
    __shared__ float tile[32][33];
    const int bx = blockIdx.x & 7;     // n-tile (8 of 32)
    const int by = blockIdx.x >> 3;    // k-tile (16 of 32)
    const int tx = threadIdx.x & 31;
    const int ty = threadIdx.x >> 5;   // 0..7
    const int n0 = bx * 32, k0 = by * 32;

    #pragma unroll
    for (int i = 0; i < 4; ++i)
        tile[ty + i * 8][tx] = W1[(size_t)(k0 + ty + i * 8) * HD + n0 + tx];
    __syncthreads();

    #pragma unroll
    for (int i = 0; i < 4; ++i) {
        int n = n0 + ty + i * 8;
        int k = k0 + tx;
        __half h = __float2half_rn(tile[tx][ty + i * 8]);
        if (k < HD) g_wd[n * HD + k]        = h;
        else        g_wt[n * HD + (k - HD)] = h;
    }
}

// ---------------------------------------------------------------------------
// HMMA GEMM:  U[M,256](fp16) = A[M,256](fp32) @ W[256,256]  (+b1 for drug)
// 64m x 256n CTA tile, BK=32. B: 3-stage cp.async pipeline (wait_group 1,
// 2-chunk lead). A: single-chunk register lookahead (R6 register footprint).
// 8 warps = 2m x 4n (32x64 each).
// ---------------------------------------------------------------------------
#define APAD   40                          // padded k-stride in halves
#define A_BYTES (2 * 64 * APAD * 2)        // 10240
#define B_BYTES (3 * 256 * APAD * 2)       // 61440
#define SMEM_TOTAL (A_BYTES + B_BYTES)     // 71680

__global__ __launch_bounds__(256, 2)
void gemm_hmma_kernel(const float* __restrict__ zd, const float* __restrict__ zt,
                      const float* __restrict__ b1) {
    extern __shared__ char smem[];
    const uint32_t sbase = smem_u32(smem);
    const uint32_t bbase = sbase + A_BYTES;

    const int blk = blockIdx.x;
    const float* A; const __half* B; __half* U; int M, bm; const float* bias;
    if (blk < NB64_D) { A = zd; B = g_wd; U = g_ud; M = N_DRUG; bm = blk * 64; bias = b1; }
    else { A = zt; B = g_wt; U = g_ut; M = N_TGT; bm = (blk - NB64_D) * 64; bias = nullptr; }

    const int tid  = threadIdx.x;
    const int lane = tid & 31;
    const int wid  = tid >> 5;
    const int wm   = (wid & 1) * 32;   // warp m offset (0/32)
    const int wn   = (wid >> 1) * 64;  // warp n offset (0/64/128/192)

    // A load mapping: 4 threads per row, 8 fp32 (2 float4) each
    const int arow = tid >> 2, aseg = tid & 3;
    const int ag   = min(bm + arow, M - 1);
    const float4* Ag = reinterpret_cast<const float4*>(A + (size_t)ag * HD);

    float acc[2][8][4];
    #pragma unroll
    for (int i = 0; i < 2; ++i)
        #pragma unroll
        for (int j = 0; j < 8; ++j)
            #pragma unroll
            for (int q = 0; q < 4; ++q) acc[i][j][q] = 0.f;

    float4 va[2];   // single-chunk A lookahead (keeps register count at R6 level)

    auto load_a = [&](int ck) {
        va[0] = Ag[ck * 8 + aseg * 2];
        va[1] = Ag[ck * 8 + aseg * 2 + 1];
    };
    auto store_a = [&](int buf) {
        uint32_t h[4];
        #pragma unroll
        for (int i = 0; i < 2; ++i) {
            __half2 p0 = __float22half2_rn(make_float2(va[i].x, va[i].y));
            __half2 p1 = __float22half2_rn(make_float2(va[i].z, va[i].w));
            h[2 * i]     = *reinterpret_cast<uint32_t*>(&p0);
            h[2 * i + 1] = *reinterpret_cast<uint32_t*>(&p1);
        }
        *reinterpret_cast<uint4*>(smem + (buf * 64 + arow) * (APAD * 2) + aseg * 16) =
            make_uint4(h[0], h[1], h[2], h[3]);
    };
    auto issue_b = [&](int ck) {
        const int st = ck % 3;
        #pragma unroll
        for (int i = 0; i < 4; ++i) {
            int idx = i * 256 + tid;          // 0..1023
            int n = idx >> 2, c = idx & 3;
            uint32_t dst = bbase + (st * 256 + n) * (APAD * 2) + c * 16;
            const __half* src = B + (size_t)n * HD + ck * 32 + c * 8;
            CP_ASYNC_16(dst, src);
        }
        CP_ASYNC_COMMIT();
    };

    // prologue: B(0),B(1) in flight; A(0) -> SMEM; A(1) -> regs; wait B(0)
    load_a(0);
    issue_b(0);
    issue_b(1);
    store_a(0);
    load_a(1);
    CP_ASYNC_WAIT1();
    __syncthreads();

    #pragma unroll 1
    for (int ck = 0; ck < 8; ++ck) {
        const int buf = ck & 1;
        const int st  = ck % 3;

        if (ck < 6) issue_b(ck + 2);          // keep 2-chunk B lead
        if (ck < 7) store_a(buf ^ 1);         // va holds A(ck+1); buffer safe (synced)
        if (ck < 6) load_a(ck + 2);           // refill va for next iteration

        #pragma unroll
        for (int ks = 0; ks < 2; ++ks) {
            uint32_t af[2][4], bf[4][4];
            #pragma unroll
            for (int mt = 0; mt < 2; ++mt) {
                uint32_t addr = sbase + (buf * 64 + wm + mt * 16 + (lane & 15)) * (APAD * 2)
                                      + (ks * 16 + (lane >> 4) * 8) * 2;
                asm volatile("ldmatrix.sync.aligned.m8n8.x4.shared.b16 {%0,%1,%2,%3}, [%4];"
                             : "=r"(af[mt][0]), "=r"(af[mt][1]), "=r"(af[mt][2]), "=r"(af[mt][3])
                             : "r"(addr));
            }
            #pragma unroll
            for (int q = 0; q < 4; ++q) {
                uint32_t addr = bbase + (st * 256 + wn + q * 16 + (lane & 15)) * (APAD * 2)
                                      + (ks * 16 + (lane >> 4) * 8) * 2;
                asm volatile("ldmatrix.sync.aligned.m8n8.x4.shared.b16 {%0,%1,%2,%3}, [%4];"
                             : "=r"(bf[q][0]), "=r"(bf[q][1]), "=r"(bf[q][2]), "=r"(bf[q][3])
                             : "r"(addr));
            }
            #pragma unroll
            for (int mt = 0; mt < 2; ++mt)
                #pragma unroll
                for (int nt = 0; nt < 8; ++nt) {
                    const int q = nt >> 1, s = nt & 1;
                    asm volatile(
                        "mma.sync.aligned.m16n8k16.row.col.f32.f16.f16.f32 "
                        "{%0,%1,%2,%3}, {%4,%5,%6,%7}, {%8,%9}, {%0,%1,%2,%3};"
                        : "+f"(acc[mt][nt][0]), "+f"(acc[mt][nt][1]),
                          "+f"(acc[mt][nt][2]), "+f"(acc[mt][nt][3])
                        : "r"(af[mt][0]), "r"(af[mt][1]), "r"(af[mt][2]), "r"(af[mt][3]),
                          "r"(bf[q][s]), "r"(bf[q][s + 2]));
                }
        }

        if (ck < 7) {
            CP_ASYNC_WAIT1();   // B(ck+1) arrived (only B(ck+2) still in flight)
            __syncthreads();
        }
    }

    // per-column bias (b1 folded into the drug table)
    float2 bv[8];
    #pragma unroll
    for (int nt = 0; nt < 8; ++nt) bv[nt] = make_float2(0.f, 0.f);
    if (bias) {
        #pragma unroll
        for (int nt = 0; nt < 8; ++nt)
            bv[nt] = *reinterpret_cast<const float2*>(bias + wn + nt * 8 + (lane & 3) * 2);
    }

    // epilogue: fp32 acc (+bias) -> fp16 U
    #pragma unroll
    for (int mt = 0; mt < 2; ++mt) {
        #pragma unroll
        for (int hr = 0; hr < 2; ++hr) {
            int r = bm + wm + mt * 16 + hr * 8 + (lane >> 2);
            if (r < M) {
                __half* up = U + (size_t)r * HD + wn + (lane & 3) * 2;
                #pragma unroll
                for (int nt = 0; nt < 8; ++nt) {
                    __half2 v = __float22half2_rn(
                        make_float2(acc[mt][nt][hr * 2] + bv[nt].x,
                                    acc[mt][nt][hr * 2 + 1] + bv[nt].y));
                    *reinterpret_cast<__half2*>(up + nt * 8) = v;
                }
            }
        }
    }
}

// ---------------------------------------------------------------------------
// Edge kernel: out[e] = relu(u_d[row[e]] + u_t[col[e]]) . W2 + b2   (b1 folded)
// 8 lanes per edge (4 edges/warp); MLP=8 per thread, 3-shuffle reduction.
// ---------------------------------------------------------------------------
__global__ __launch_bounds__(256)
void edge_kernel(const void* __restrict__ rowp, const void* __restrict__ colp,
                 const float* __restrict__ W2, const float* __restrict__ b2,
                 float* __restrict__ out, int E) {
    __shared__ float s_w2[HD];
    const int tid = threadIdx.x;
    s_w2[tid] = W2[tid];
    __syncthreads();

    const int lane = tid & 31;
    const int wid  = tid >> 5;
    const int sub  = lane & 7;
    const int g    = lane >> 3;

    float w2r[32];
    #pragma unroll
    for (int i = 0; i < 4; ++i) {
        float4 v0 = *reinterpret_cast<const float4*>(&s_w2[(i * 8 + sub) * 8]);
        float4 v1 = *reinterpret_cast<const float4*>(&s_w2[(i * 8 + sub) * 8 + 4]);
        w2r[i * 8 + 0] = v0.x; w2r[i * 8 + 1] = v0.y;
        w2r[i * 8 + 2] = v0.z; w2r[i * 8 + 3] = v0.w;
        w2r[i * 8 + 4] = v1.x; w2r[i * 8 + 5] = v1.y;
        w2r[i * 8 + 6] = v1.z; w2r[i * 8 + 7] = v1.w;
    }
    const float bias2 = b2[0];
    const bool idx64 = (g_idx64 != 0);
    const __half2 zero2 = __float2half2_rn(0.f);

    for (int e = blockIdx.x * 32 + wid * 4 + g; e < E; e += gridDim.x * 32) {
        long long r, c;
        if (idx64) {
            r = reinterpret_cast<const long long*>(rowp)[e];
            c = reinterpret_cast<const long long*>(colp)[e];
        } else {
            r = reinterpret_cast<const int*>(rowp)[e];
            c = reinterpret_cast<const int*>(colp)[e];
        }
        const uint4* ap = reinterpret_cast<const uint4*>(g_ud + (size_t)r * HD);
        const uint4* bp = reinterpret_cast<const uint4*>(g_ut + (size_t)c * HD);

        uint4 av[4], bv[4];
        #pragma unroll
        for (int i = 0; i < 4; ++i) av[i] = ap[i * 8 + sub];
        #pragma unroll
        for (int i = 0; i < 4; ++i) bv[i] = bp[i * 8 + sub];

        float sum = 0.f;
        #pragma unroll
        for (int i = 0; i < 4; ++i) {
            const __half2* ah = reinterpret_cast<const __half2*>(&av[i]);
            const __half2* bh = reinterpret_cast<const __half2*>(&bv[i]);
            #pragma unroll
            for (int j = 0; j < 4; ++j) {
                __half2 h = __hmax2(__hadd2(ah[j], bh[j]), zero2);
                float2 f = __half22float2(h);
                sum = fmaf(f.x, w2r[i * 8 + j * 2],     sum);
                sum = fmaf(f.y, w2r[i * 8 + j * 2 + 1], sum);
            }
        }

        sum += __shfl_xor_sync(0xffffffffu, sum, 4);
        sum += __shfl_xor_sync(0xffffffffu, sum, 2);
        sum += __shfl_xor_sync(0xffffffffu, sum, 1);
        if (sub == 0) out[e] = sum + bias2;
    }
}

// ---------------------------------------------------------------------------
// inputs: 0=z_drug 1=z_target 2=row 3=col 4=W1[512,256] 5=b1 6=W2 7=b2
// ---------------------------------------------------------------------------
extern "C" void kernel_launch(void* const* d_in, const int* in_sizes, int n_in,
                              void* d_out, int out_size) {
    const float* z_drug   = (const float*)d_in[0];
    const float* z_target = (const float*)d_in[1];
    const void*  rowp     = d_in[2];
    const void*  colp     = d_in[3];
    const float* W1       = (const float*)d_in[4];
    const float* b1       = (const float*)d_in[5];
    const float* W2       = (const float*)d_in[6];
    const float* b2       = (const float*)d_in[7];
    float* out = (float*)d_out;
    const int E = out_size;

    cudaFuncSetAttribute(gemm_hmma_kernel,
                         cudaFuncAttributeMaxDynamicSharedMemorySize, SMEM_TOTAL);

    prep_w1_kernel<<<128, 256>>>(W1, (const unsigned long long*)rowp);
    gemm_hmma_kernel<<<NB64_D + NB64_T, 256, SMEM_TOTAL>>>(z_drug, z_target, b1);
    edge_kernel<<<2048, 256>>>(rowp, colp, W2, b2, out, E);
}

// round 14
// speedup vs baseline: 1.0030x; 1.0020x over previous
#include <cuda_runtime.h>
#include <cuda_fp16.h>
#include <stdint.h>

#define HD      256
#define N_DRUG  50000
#define N_TGT   20000
#define NB64_D  782   // ceil(50000/64)
#define NB64_T  313   // ceil(20000/64)

// ---------------- device scratch (no allocation allowed) -------------------
__device__ __align__(16) __half g_ud[(size_t)N_DRUG * HD];   // fp16, b1 folded in
__device__ __align__(16) __half g_ut[(size_t)N_TGT  * HD];
// W1 transposed to [n][k] fp16 (K-contiguous rows => col-major B for mma.sync)
__device__ __align__(16) __half g_wd[HD * HD];
__device__ __align__(16) __half g_wt[HD * HD];
__device__ int g_idx64;

__device__ __forceinline__ uint32_t smem_u32(const void* p) {
    uint32_t a;
    asm("{ .reg .u64 t; cvta.to.shared.u64 t, %1; cvt.u32.u64 %0, t; }" : "=r"(a) : "l"(p));
    return a;
}
#define CP_ASYNC_16(dst, src) \
    asm volatile("cp.async.cg.shared.global [%0], [%1], 16;" :: "r"(dst), "l"(src))
#define CP_ASYNC_COMMIT() asm volatile("cp.async.commit_group;")
#define CP_ASYNC_WAIT1()  asm volatile("cp.async.wait_group 1;")

// ---------------------------------------------------------------------------
// W1 prep: 32x32 SMEM-tiled transpose [k][n] -> [n][k] + fp32->fp16.
// Coalesced reads AND writes (R6/R8 version scattered 2B stores at 512B
// stride -> 32 sectors/warp; that was the 5.6us). Block 0 warp 0 also does
// the int64-vs-int32 index-width detect (ballot).
// ---------------------------------------------------------------------------
__global__ void prep_w1_kernel(const float* __restrict__ W1,
                               const unsigned long long* __restrict__ row) {
    if (blockIdx.x == 0 && threadIdx.x < 32) {
        unsigned long long v0 = row[threadIdx.x];
        unsigned long long v1 = row[threadIdx.x + 32];
        int bad = (v0 >= (unsigned long long)N_DRUG) ||
                  (v1 >= (unsigned long long)N_DRUG);
        unsigned m = __ballot_sync(0xffffffffu, bad);
        if (threadIdx.x == 0) g_idx64 = (m == 0);
    }
    __shared__ float tile[32][33];
    const int bx = blockIdx.x & 7;     // n-tile (8 of 32)
    const int by = blockIdx.x >> 3;    // k-tile (16 of 32)
    const int tx = threadIdx.x & 31;
    const int ty = threadIdx.x >> 5;   // 0..7
    const int n0 = bx * 32, k0 = by * 32;

    #pragma unroll
    for (int i = 0; i < 4; ++i)
        tile[ty + i * 8][tx] = W1[(size_t)(k0 + ty + i * 8) * HD + n0 + tx];
    __syncthreads();

    #pragma unroll
    for (int i = 0; i < 4; ++i) {
        int n = n0 + ty + i * 8;
        int k = k0 + tx;
        __half h = __float2half_rn(tile[tx][ty + i * 8]);
        if (k < HD) g_wd[n * HD + k]        = h;
        else        g_wt[n * HD + (k - HD)] = h;
    }
}

// ---------------------------------------------------------------------------
// HMMA GEMM:  U[M,256](fp16) = A[M,256](fp32) @ W[256,256]  (+b1 for drug)
// 64m x 256n CTA tile, BK=32. B: 3-stage cp.async pipeline (wait_group 1,
// 2-chunk lead). A: single-chunk register lookahead (R6 register footprint).
// 8 warps = 2m x 4n (32x64 each).
// ---------------------------------------------------------------------------
#define APAD   40                          // padded k-stride in halves
#define A_BYTES (2 * 64 * APAD * 2)        // 10240
#define B_BYTES (3 * 256 * APAD * 2)       // 61440
#define SMEM_TOTAL (A_BYTES + B_BYTES)     // 71680

__global__ __launch_bounds__(256, 2)
void gemm_hmma_kernel(const float* __restrict__ zd, const float* __restrict__ zt,
                      const float* __restrict__ b1) {
    extern __shared__ char smem[];
    const uint32_t sbase = smem_u32(smem);
    const uint32_t bbase = sbase + A_BYTES;

    const int blk = blockIdx.x;
    const float* A; const __half* B; __half* U; int M, bm; const float* bias;
    if (blk < NB64_D) { A = zd; B = g_wd; U = g_ud; M = N_DRUG; bm = blk * 64; bias = b1; }
    else { A = zt; B = g_wt; U = g_ut; M = N_TGT; bm = (blk - NB64_D) * 64; bias = nullptr; }

    const int tid  = threadIdx.x;
    const int lane = tid & 31;
    const int wid  = tid >> 5;
    const int wm   = (wid & 1) * 32;   // warp m offset (0/32)
    const int wn   = (wid >> 1) * 64;  // warp n offset (0/64/128/192)

    // A load mapping: 4 threads per row, 8 fp32 (2 float4) each
    const int arow = tid >> 2, aseg = tid & 3;
    const int ag   = min(bm + arow, M - 1);
    const float4* Ag = reinterpret_cast<const float4*>(A + (size_t)ag * HD);

    float acc[2][8][4];
    #pragma unroll
    for (int i = 0; i < 2; ++i)
        #pragma unroll
        for (int j = 0; j < 8; ++j)
            #pragma unroll
            for (int q = 0; q < 4; ++q) acc[i][j][q] = 0.f;

    float4 va[2];   // single-chunk A lookahead (keeps register count at R6 level)

    auto load_a = [&](int ck) {
        va[0] = Ag[ck * 8 + aseg * 2];
        va[1] = Ag[ck * 8 + aseg * 2 + 1];
    };
    auto store_a = [&](int buf) {
        uint32_t h[4];
        #pragma unroll
        for (int i = 0; i < 2; ++i) {
            __half2 p0 = __float22half2_rn(make_float2(va[i].x, va[i].y));
            __half2 p1 = __float22half2_rn(make_float2(va[i].z, va[i].w));
            h[2 * i]     = *reinterpret_cast<uint32_t*>(&p0);
            h[2 * i + 1] = *reinterpret_cast<uint32_t*>(&p1);
        }
        *reinterpret_cast<uint4*>(smem + (buf * 64 + arow) * (APAD * 2) + aseg * 16) =
            make_uint4(h[0], h[1], h[2], h[3]);
    };
    auto issue_b = [&](int ck) {
        const int st = ck % 3;
        #pragma unroll
        for (int i = 0; i < 4; ++i) {
            int idx = i * 256 + tid;          // 0..1023
            int n = idx >> 2, c = idx & 3;
            uint32_t dst = bbase + (st * 256 + n) * (APAD * 2) + c * 16;
            const __half* src = B + (size_t)n * HD + ck * 32 + c * 8;
            CP_ASYNC_16(dst, src);
        }
        CP_ASYNC_COMMIT();
    };

    // prologue: B(0),B(1) in flight; A(0) -> SMEM; A(1) -> regs; wait B(0)
    load_a(0);
    issue_b(0);
    issue_b(1);
    store_a(0);
    load_a(1);
    CP_ASYNC_WAIT1();
    __syncthreads();

    #pragma unroll 1
    for (int ck = 0; ck < 8; ++ck) {
        const int buf = ck & 1;
        const int st  = ck % 3;

        if (ck < 6) issue_b(ck + 2);          // keep 2-chunk B lead
        if (ck < 7) store_a(buf ^ 1);         // va holds A(ck+1); buffer safe (synced)
        if (ck < 6) load_a(ck + 2);           // refill va for next iteration

        #pragma unroll
        for (int ks = 0; ks < 2; ++ks) {
            uint32_t af[2][4], bf[4][4];
            #pragma unroll
            for (int mt = 0; mt < 2; ++mt) {
                uint32_t addr = sbase + (buf * 64 + wm + mt * 16 + (lane & 15)) * (APAD * 2)
                                      + (ks * 16 + (lane >> 4) * 8) * 2;
                asm volatile("ldmatrix.sync.aligned.m8n8.x4.shared.b16 {%0,%1,%2,%3}, [%4];"
                             : "=r"(af[mt][0]), "=r"(af[mt][1]), "=r"(af[mt][2]), "=r"(af[mt][3])
                             : "r"(addr));
            }
            #pragma unroll
            for (int q = 0; q < 4; ++q) {
                uint32_t addr = bbase + (st * 256 + wn + q * 16 + (lane & 15)) * (APAD * 2)
                                      + (ks * 16 + (lane >> 4) * 8) * 2;
                asm volatile("ldmatrix.sync.aligned.m8n8.x4.shared.b16 {%0,%1,%2,%3}, [%4];"
                             : "=r"(bf[q][0]), "=r"(bf[q][1]), "=r"(bf[q][2]), "=r"(bf[q][3])
                             : "r"(addr));
            }
            #pragma unroll
            for (int mt = 0; mt < 2; ++mt)
                #pragma unroll
                for (int nt = 0; nt < 8; ++nt) {
                    const int q = nt >> 1, s = nt & 1;
                    asm volatile(
                        "mma.sync.aligned.m16n8k16.row.col.f32.f16.f16.f32 "
                        "{%0,%1,%2,%3}, {%4,%5,%6,%7}, {%8,%9}, {%0,%1,%2,%3};"
                        : "+f"(acc[mt][nt][0]), "+f"(acc[mt][nt][1]),
                          "+f"(acc[mt][nt][2]), "+f"(acc[mt][nt][3])
                        : "r"(af[mt][0]), "r"(af[mt][1]), "r"(af[mt][2]), "r"(af[mt][3]),
                          "r"(bf[q][s]), "r"(bf[q][s + 2]));
                }
        }

        if (ck < 7) {
            CP_ASYNC_WAIT1();   // B(ck+1) arrived (only B(ck+2) still in flight)
            __syncthreads();
        }
    }

    // per-column bias (b1 folded into the drug table)
    float2 bv[8];
    #pragma unroll
    for (int nt = 0; nt < 8; ++nt) bv[nt] = make_float2(0.f, 0.f);
    if (bias) {
        #pragma unroll
        for (int nt = 0; nt < 8; ++nt)
            bv[nt] = *reinterpret_cast<const float2*>(bias + wn + nt * 8 + (lane & 3) * 2);
    }

    // epilogue: fp32 acc (+bias) -> fp16 U
    #pragma unroll
    for (int mt = 0; mt < 2; ++mt) {
        #pragma unroll
        for (int hr = 0; hr < 2; ++hr) {
            int r = bm + wm + mt * 16 + hr * 8 + (lane >> 2);
            if (r < M) {
                __half* up = U + (size_t)r * HD + wn + (lane & 3) * 2;
                #pragma unroll
                for (int nt = 0; nt < 8; ++nt) {
                    __half2 v = __float22half2_rn(
                        make_float2(acc[mt][nt][hr * 2] + bv[nt].x,
                                    acc[mt][nt][hr * 2 + 1] + bv[nt].y));
                    *reinterpret_cast<__half2*>(up + nt * 8) = v;
                }
            }
        }
    }
}

// ---------------------------------------------------------------------------
// Edge kernel: out[e] = relu(u_d[row[e]] + u_t[col[e]]) . W2 + b2   (b1 folded)
// 8 lanes per edge (4 edges/warp); MLP=8 per thread, 3-shuffle reduction.
// ---------------------------------------------------------------------------
__global__ __launch_bounds__(256)
void edge_kernel(const void* __restrict__ rowp, const void* __restrict__ colp,
                 const float* __restrict__ W2, const float* __restrict__ b2,
                 float* __restrict__ out, int E) {
    __shared__ float s_w2[HD];
    const int tid = threadIdx.x;
    s_w2[tid] = W2[tid];
    __syncthreads();

    const int lane = tid & 31;
    const int wid  = tid >> 5;
    const int sub  = lane & 7;
    const int g    = lane >> 3;

    float w2r[32];
    #pragma unroll
    for (int i = 0; i < 4; ++i) {
        float4 v0 = *reinterpret_cast<const float4*>(&s_w2[(i * 8 + sub) * 8]);
        float4 v1 = *reinterpret_cast<const float4*>(&s_w2[(i * 8 + sub) * 8 + 4]);
        w2r[i * 8 + 0] = v0.x; w2r[i * 8 + 1] = v0.y;
        w2r[i * 8 + 2] = v0.z; w2r[i * 8 + 3] = v0.w;
        w2r[i * 8 + 4] = v1.x; w2r[i * 8 + 5] = v1.y;
        w2r[i * 8 + 6] = v1.z; w2r[i * 8 + 7] = v1.w;
    }
    const float bias2 = b2[0];
    const bool idx64 = (g_idx64 != 0);
    const __half2 zero2 = __float2half2_rn(0.f);

    for (int e = blockIdx.x * 32 + wid * 4 + g; e < E; e += gridDim.x * 32) {
        long long r, c;
        if (idx64) {
            r = reinterpret_cast<const long long*>(rowp)[e];
            c = reinterpret_cast<const long long*>(colp)[e];
        } else {
            r = reinterpret_cast<const int*>(rowp)[e];
            c = reinterpret_cast<const int*>(colp)[e];
        }
        const uint4* ap = reinterpret_cast<const uint4*>(g_ud + (size_t)r * HD);
        const uint4* bp = reinterpret_cast<const uint4*>(g_ut + (size_t)c * HD);

        uint4 av[4], bv[4];
        #pragma unroll
        for (int i = 0; i < 4; ++i) av[i] = ap[i * 8 + sub];
        #pragma unroll
        for (int i = 0; i < 4; ++i) bv[i] = bp[i * 8 + sub];

        float sum = 0.f;
        #pragma unroll
        for (int i = 0; i < 4; ++i) {
            const __half2* ah = reinterpret_cast<const __half2*>(&av[i]);
            const __half2* bh = reinterpret_cast<const __half2*>(&bv[i]);
            #pragma unroll
            for (int j = 0; j < 4; ++j) {
                __half2 h = __hmax2(__hadd2(ah[j], bh[j]), zero2);
                float2 f = __half22float2(h);
                sum = fmaf(f.x, w2r[i * 8 + j * 2],     sum);
                sum = fmaf(f.y, w2r[i * 8 + j * 2 + 1], sum);
            }
        }

        sum += __shfl_xor_sync(0xffffffffu, sum, 4);
        sum += __shfl_xor_sync(0xffffffffu, sum, 2);
        sum += __shfl_xor_sync(0xffffffffu, sum, 1);
        if (sub == 0) out[e] = sum + bias2;
    }
}

// ---------------------------------------------------------------------------
// inputs: 0=z_drug 1=z_target 2=row 3=col 4=W1[512,256] 5=b1 6=W2 7=b2
// ---------------------------------------------------------------------------
extern "C" void kernel_launch(void* const* d_in, const int* in_sizes, int n_in,
                              void* d_out, int out_size) {
    const float* z_drug   = (const float*)d_in[0];
    const float* z_target = (const float*)d_in[1];
    const void*  rowp     = d_in[2];
    const void*  colp     = d_in[3];
    const float* W1       = (const float*)d_in[4];
    const float* b1       = (const float*)d_in[5];
    const float* W2       = (const float*)d_in[6];
    const float* b2       = (const float*)d_in[7];
    float* out = (float*)d_out;
    const int E = out_size;

    cudaFuncSetAttribute(gemm_hmma_kernel,
                         cudaFuncAttributeMaxDynamicSharedMemorySize, SMEM_TOTAL);

    prep_w1_kernel<<<128, 256>>>(W1, (const unsigned long long*)rowp);
    gemm_hmma_kernel<<<NB64_D + NB64_T, 256, SMEM_TOTAL>>>(z_drug, z_target, b1);
    edge_kernel<<<2048, 256>>>(rowp, colp, W2, b2, out, E);
}